// round 14
// baseline (speedup 1.0000x reference)
#include <cuda_runtime.h>
#include <cuda_bf16.h>
#include <cstdint>
#include <cstddef>

// Problem constants
constexpr int B   = 2;
constexpr int T   = 2048;
constexpr int DIM = 1024;
constexpr int H   = 16;
constexpr int HD  = 64;
constexpr int BT  = B * T;        // 4096
constexpr float SCALE = 0.03125f; // 1/sqrt(1024)
constexpr float LOG2E = 1.44269504088896341f;
constexpr float QMUL  = SCALE * LOG2E;   // fold into q projection

constexpr size_t Y_SIZE   = (size_t)BT * DIM;
constexpr size_t ATT_SIZE = (size_t)B * H * T * T;

// Scratch (allocation-free rule: __device__ globals)
// pre-split inputs / weights
__device__ __nv_bfloat16 g_xqhi[BT * DIM], g_xqlo[BT * DIM];
__device__ __nv_bfloat16 g_xkhi[BT * DIM], g_xklo[BT * DIM];
__device__ __nv_bfloat16 g_xvhi[BT * DIM], g_xvlo[BT * DIM];
__device__ __nv_bfloat16 g_wqhi[DIM * DIM], g_wqlo[DIM * DIM];
__device__ __nv_bfloat16 g_wkhi[DIM * DIM], g_wklo[DIM * DIM];
__device__ __nv_bfloat16 g_wvhi[DIM * DIM], g_wvlo[DIM * DIM];
__device__ __nv_bfloat16 g_wohi[DIM * DIM], g_wolo[DIM * DIM];
// projection outputs (pre-split)
__device__ __nv_bfloat16 g_qhi[BT * DIM], g_qlo[BT * DIM];
__device__ __nv_bfloat16 g_khi[BT * DIM], g_klo[BT * DIM];
__device__ __nv_bfloat16 g_vhi[BT * DIM], g_vlo[BT * DIM];
// attention output y (pre-split)
__device__ __nv_bfloat16 g_yhi[BT * DIM], g_ylo[BT * DIM];
__device__ float g_att_fb[ATT_SIZE];   // fallback att if out buffer lacks room

// ===========================================================================
// PTX helpers (standard ISA — legal on plain sm_103 target)
// ===========================================================================
__device__ __forceinline__ uint32_t smem_u32(const void* p) {
    uint32_t a;
    asm("{ .reg .u64 t; cvta.to.shared.u64 t, %1; cvt.u32.u64 %0, t; }" : "=r"(a) : "l"(p));
    return a;
}
__device__ __forceinline__ void ldsm_x4(uint32_t& r0, uint32_t& r1, uint32_t& r2,
                                        uint32_t& r3, uint32_t addr) {
    asm volatile("ldmatrix.sync.aligned.m8n8.x4.shared.b16 {%0,%1,%2,%3}, [%4];"
                 : "=r"(r0), "=r"(r1), "=r"(r2), "=r"(r3) : "r"(addr));
}
__device__ __forceinline__ void ldsm_x2(uint32_t& r0, uint32_t& r1, uint32_t addr) {
    asm volatile("ldmatrix.sync.aligned.m8n8.x2.shared.b16 {%0,%1}, [%2];"
                 : "=r"(r0), "=r"(r1) : "r"(addr));
}
__device__ __forceinline__ void ldsm_x2_t(uint32_t& r0, uint32_t& r1, uint32_t addr) {
    asm volatile("ldmatrix.sync.aligned.m8n8.x2.trans.shared.b16 {%0,%1}, [%2];"
                 : "=r"(r0), "=r"(r1) : "r"(addr));
}
__device__ __forceinline__ void mma_bf16(float* c, const uint32_t* a, const uint32_t* b) {
    asm volatile(
        "mma.sync.aligned.m16n8k16.row.col.f32.bf16.bf16.f32 "
        "{%0,%1,%2,%3}, {%4,%5,%6,%7}, {%8,%9}, {%0,%1,%2,%3};"
        : "+f"(c[0]), "+f"(c[1]), "+f"(c[2]), "+f"(c[3])
        : "r"(a[0]), "r"(a[1]), "r"(a[2]), "r"(a[3]), "r"(b[0]), "r"(b[1]));
}
__device__ __forceinline__ void cp16(uint32_t dst, const void* src) {
    asm volatile("cp.async.ca.shared.global [%0], [%1], 16;" :: "r"(dst), "l"(src));
}
__device__ __forceinline__ void cp_commit() {
    asm volatile("cp.async.commit_group;" ::: "memory");
}
template <int N>
__device__ __forceinline__ void cp_wait() {
    asm volatile("cp.async.wait_group %0;" :: "n"(N) : "memory");
}
__device__ __forceinline__ void split4(float4 v, uint2& hi, uint2& lo) {
    __nv_bfloat16 h0 = __float2bfloat16_rn(v.x);
    __nv_bfloat16 h1 = __float2bfloat16_rn(v.y);
    __nv_bfloat16 h2 = __float2bfloat16_rn(v.z);
    __nv_bfloat16 h3 = __float2bfloat16_rn(v.w);
    __nv_bfloat16 l0 = __float2bfloat16_rn(v.x - __bfloat162float(h0));
    __nv_bfloat16 l1 = __float2bfloat16_rn(v.y - __bfloat162float(h1));
    __nv_bfloat16 l2 = __float2bfloat16_rn(v.z - __bfloat162float(h2));
    __nv_bfloat16 l3 = __float2bfloat16_rn(v.w - __bfloat162float(h3));
    __nv_bfloat162 hA = {h0, h1}, hB = {h2, h3}, lA = {l0, l1}, lB = {l2, l3};
    hi = make_uint2(*(uint32_t*)&hA, *(uint32_t*)&hB);
    lo = make_uint2(*(uint32_t*)&lA, *(uint32_t*)&lB);
}
__device__ __forceinline__ void pack2(float x, float y, uint32_t& hi, uint32_t& lo) {
    __nv_bfloat16 hx = __float2bfloat16_rn(x);
    __nv_bfloat16 hy = __float2bfloat16_rn(y);
    __nv_bfloat162 hp = {hx, hy};
    __nv_bfloat162 lp = {__float2bfloat16_rn(x - __bfloat162float(hx)),
                         __float2bfloat16_rn(y - __bfloat162float(hy))};
    hi = *(uint32_t*)&hp;
    lo = *(uint32_t*)&lp;
}

// ===========================================================================
// Conversion pass: fp32 -> bf16 hi/lo for inputs + weights (one elementwise kernel)
// z: 0..2 inputs (4M elems), 3..6 weights (1M elems)
// ===========================================================================
__global__ __launch_bounds__(256)
void conv_split(const float* __restrict__ s0, const float* __restrict__ s1,
                const float* __restrict__ s2, const float* __restrict__ s3,
                const float* __restrict__ s4, const float* __restrict__ s5,
                const float* __restrict__ s6) {
    const int z = blockIdx.y;
    const float* s;
    __nv_bfloat16 *h, *l;
    int n4;
    switch (z) {
        case 0: s = s0; h = g_xqhi; l = g_xqlo; n4 = BT * DIM / 4; break;
        case 1: s = s1; h = g_xkhi; l = g_xklo; n4 = BT * DIM / 4; break;
        case 2: s = s2; h = g_xvhi; l = g_xvlo; n4 = BT * DIM / 4; break;
        case 3: s = s3; h = g_wqhi; l = g_wqlo; n4 = DIM * DIM / 4; break;
        case 4: s = s4; h = g_wkhi; l = g_wklo; n4 = DIM * DIM / 4; break;
        case 5: s = s5; h = g_wvhi; l = g_wvlo; n4 = DIM * DIM / 4; break;
        default: s = s6; h = g_wohi; l = g_wolo; n4 = DIM * DIM / 4; break;
    }
    for (int i = blockIdx.x * 256 + threadIdx.x; i < n4; i += gridDim.x * 256) {
        float4 v = ((const float4*)s)[i];
        uint2 hi, lo;
        split4(v, hi, lo);
        ((uint2*)h)[i] = hi;
        ((uint2*)l)[i] = lo;
    }
}

// ===========================================================================
// Pure-bf16 GEMM core: C = A @ W^T, 128x128 tile, K-chunk 32,
// cp.async double-buffered, conversion-free inner loop.
// ===========================================================================
constexpr int KDIM = 1024;
constexpr int NDIM = 1024;
constexpr int GKCH = 32;
constexpr int GNCH = KDIM / GKCH;   // 32 chunks
constexpr int GP   = 40;            // smem row pad (bf16)
constexpr int GBUF = 128 * GP;      // elems per operand buffer
constexpr int GEMM_SMEM = 2 * 4 * GBUF * 2;   // 81,920 B

struct EpiSplit {           // write bf16 hi/lo with scale
    __nv_bfloat16* Chi;
    __nv_bfloat16* Clo;
    float mul;
    __device__ __forceinline__ void operator()(int r0, int cc, const float* cf) const {
#pragma unroll
        for (int rr = 0; rr < 2; ++rr) {
            const size_t off = (size_t)(r0 + rr * 8) * NDIM + cc;
            uint32_t hp, lp;
            pack2(cf[rr * 2] * mul, cf[rr * 2 + 1] * mul, hp, lp);
            *(uint32_t*)(Chi + off) = hp;
            *(uint32_t*)(Clo + off) = lp;
        }
    }
};
struct EpiF32 {             // write fp32
    float* C;
    __device__ __forceinline__ void operator()(int r0, int cc, const float* cf) const {
        *(float2*)(C + (size_t)r0 * NDIM + cc)       = make_float2(cf[0], cf[1]);
        *(float2*)(C + (size_t)(r0 + 8) * NDIM + cc) = make_float2(cf[2], cf[3]);
    }
};

// cp one 128x32 bf16 chunk x4 operands into stage buffers
__device__ __forceinline__ void gemm_cp_chunk(
    uint32_t ah, uint32_t al, uint32_t wh, uint32_t wl,
    const __nv_bfloat16* __restrict__ Ahi, const __nv_bfloat16* __restrict__ Alo,
    const __nv_bfloat16* __restrict__ Whi, const __nv_bfloat16* __restrict__ Wlo,
    size_t aoff, size_t woff, int tid) {
#pragma unroll
    for (int i = 0; i < 2; ++i) {
        const int idx = tid * 2 + i;            // 0..511
        const int row = idx >> 2, c8 = (idx & 3) * 8;
        const uint32_t d = (uint32_t)((row * GP + c8) * 2);
        const size_t ga = aoff + (size_t)row * KDIM + c8;
        const size_t gw = woff + (size_t)row * KDIM + c8;
        cp16(ah + d, Ahi + ga);
        cp16(al + d, Alo + ga);
        cp16(wh + d, Whi + gw);
        cp16(wl + d, Wlo + gw);
    }
}

template <typename EPI>
__device__ __forceinline__ void gemm_core(
    const __nv_bfloat16* __restrict__ Ahi, const __nv_bfloat16* __restrict__ Alo,
    const __nv_bfloat16* __restrict__ Whi, const __nv_bfloat16* __restrict__ Wlo,
    int m0, int n0, EPI epi) {
    extern __shared__ __nv_bfloat16 sg[];
    // layout: [stage(2)][operand(4: Ahi,Alo,Whi,Wlo)][128*GP]
    const int tid  = threadIdx.x;
    const int wid  = tid >> 5;
    const int lane = tid & 31;
    const int warp_m = wid >> 2;
    const int warp_n = wid & 3;

    __nv_bfloat16* sAh[2] = { sg + 0 * GBUF, sg + 4 * GBUF };
    __nv_bfloat16* sAl[2] = { sg + 1 * GBUF, sg + 5 * GBUF };
    __nv_bfloat16* sWh[2] = { sg + 2 * GBUF, sg + 6 * GBUF };
    __nv_bfloat16* sWl[2] = { sg + 3 * GBUF, sg + 7 * GBUF };
    uint32_t aAh[2] = { smem_u32(sAh[0]), smem_u32(sAh[1]) };
    uint32_t aAl[2] = { smem_u32(sAl[0]), smem_u32(sAl[1]) };
    uint32_t aWh[2] = { smem_u32(sWh[0]), smem_u32(sWh[1]) };
    uint32_t aWl[2] = { smem_u32(sWl[0]), smem_u32(sWl[1]) };

    const size_t abase = (size_t)m0 * KDIM;
    const size_t wbase = (size_t)n0 * KDIM;

    float c[4][4][4] = {};

    gemm_cp_chunk(aAh[0], aAl[0], aWh[0], aWl[0], Ahi, Alo, Whi, Wlo, abase, wbase, tid);
    cp_commit();

    for (int ch = 0; ch < GNCH; ++ch) {
        const int bf = ch & 1;
        if (ch + 1 < GNCH) {
            const size_t ko = (size_t)(ch + 1) * GKCH;
            gemm_cp_chunk(aAh[bf ^ 1], aAl[bf ^ 1], aWh[bf ^ 1], aWl[bf ^ 1],
                          Ahi, Alo, Whi, Wlo, abase + ko, wbase + ko, tid);
            cp_commit();
            cp_wait<1>();
        } else {
            cp_wait<0>();
        }
        __syncthreads();

#pragma unroll
        for (int ks = 0; ks < 2; ++ks) {
            const int kc = ks * 16;
            uint32_t ah[4][4], al[4][4], bh[4][2], bl[4][2];
#pragma unroll
            for (int mt = 0; mt < 4; ++mt) {
                const int r   = warp_m * 64 + mt * 16 + (lane & 15);
                const int col = kc + ((lane >> 4) << 3);
                ldsm_x4(ah[mt][0], ah[mt][1], ah[mt][2], ah[mt][3],
                        smem_u32(&sAh[bf][r * GP + col]));
                ldsm_x4(al[mt][0], al[mt][1], al[mt][2], al[mt][3],
                        smem_u32(&sAl[bf][r * GP + col]));
            }
#pragma unroll
            for (int nt = 0; nt < 4; ++nt) {
                const int t   = lane & 15;
                const int r   = warp_n * 32 + nt * 8 + (t & 7);
                const int col = kc + ((t >> 3) << 3);
                ldsm_x2(bh[nt][0], bh[nt][1], smem_u32(&sWh[bf][r * GP + col]));
                ldsm_x2(bl[nt][0], bl[nt][1], smem_u32(&sWl[bf][r * GP + col]));
            }
#pragma unroll
            for (int mt = 0; mt < 4; ++mt)
#pragma unroll
                for (int nt = 0; nt < 4; ++nt) {
                    mma_bf16(c[mt][nt], ah[mt], bh[nt]);
                    mma_bf16(c[mt][nt], ah[mt], bl[nt]);
                    mma_bf16(c[mt][nt], al[mt], bh[nt]);
                }
        }
        __syncthreads();
    }

#pragma unroll
    for (int mt = 0; mt < 4; ++mt) {
        const int r0 = m0 + warp_m * 64 + mt * 16 + (lane >> 2);
#pragma unroll
        for (int nt = 0; nt < 4; ++nt) {
            const int cc = n0 + warp_n * 32 + nt * 8 + (lane & 3) * 2;
            epi(r0, cc, c[mt][nt]);
        }
    }
}

// Merged Q/K/V projection (z selects); Q output pre-scaled by QMUL.
__global__ __launch_bounds__(256, 1)
void gemm_qkv() {
    const int z = blockIdx.z;
    const __nv_bfloat16 *Ahi, *Alo, *Whi, *Wlo;
    EpiSplit epi;
    if (z == 0) { Ahi = g_xqhi; Alo = g_xqlo; Whi = g_wqhi; Wlo = g_wqlo;
                  epi.Chi = g_qhi; epi.Clo = g_qlo; epi.mul = QMUL; }
    else if (z == 1) { Ahi = g_xkhi; Alo = g_xklo; Whi = g_wkhi; Wlo = g_wklo;
                  epi.Chi = g_khi; epi.Clo = g_klo; epi.mul = 1.0f; }
    else { Ahi = g_xvhi; Alo = g_xvlo; Whi = g_wvhi; Wlo = g_wvlo;
                  epi.Chi = g_vhi; epi.Clo = g_vlo; epi.mul = 1.0f; }
    gemm_core(Ahi, Alo, Whi, Wlo, blockIdx.y * 128, blockIdx.x * 128, epi);
}

// Output projection: y (pre-split) @ Wo^T -> fp32.
__global__ __launch_bounds__(256, 1)
void gemm_out(float* __restrict__ C) {
    EpiF32 epi;
    epi.C = C;
    gemm_core(g_yhi, g_ylo, g_wohi, g_wolo, blockIdx.y * 128, blockIdx.x * 128, epi);
}

// ===========================================================================
// Fused flash attention with cp.async double-buffered K/V tiles.
// Scores in log2 units (q pre-scaled by SCALE*log2e) -> exp2f.
// y written as bf16 hi/lo for the output projection.
// ===========================================================================
constexpr int FPAD  = 72;
constexpr int TILEB = 128 * FPAD;
constexpr int FUSED_SMEM = 10 * TILEB * 2;        // 184,320 B

__device__ __forceinline__ void cp_tile(uint32_t dh, uint32_t dl,
                                        const __nv_bfloat16* __restrict__ gh,
                                        const __nv_bfloat16* __restrict__ gl,
                                        size_t gbase, int tid) {
#pragma unroll
    for (int i = 0; i < 4; ++i) {
        const int idx = tid + i * 256;
        const int row = idx >> 3, c8 = (idx & 7) * 8;
        const size_t off = gbase + (size_t)row * DIM + c8;
        const uint32_t d = (uint32_t)((row * FPAD + c8) * 2);
        cp16(dh + d, gh + off);
        cp16(dl + d, gl + off);
    }
}

__device__ __forceinline__ void compute_scores(
    const __nv_bfloat16* __restrict__ sKh, const __nv_bfloat16* __restrict__ sKl,
    const uint32_t qh[4][4], const uint32_t ql[4][4],
    int lane, float c[16][4]) {
#pragma unroll
    for (int nt = 0; nt < 16; ++nt) {
        c[nt][0] = 0.f; c[nt][1] = 0.f; c[nt][2] = 0.f; c[nt][3] = 0.f;
    }
    const int t15 = lane & 15;
#pragma unroll
    for (int ks = 0; ks < 4; ++ks) {
        const int col = ks * 16 + ((t15 >> 3) << 3);
#pragma unroll
        for (int ng = 0; ng < 4; ++ng) {
            uint32_t bhf[4][2], blf[4][2];
#pragma unroll
            for (int q = 0; q < 4; ++q) {
                const int r = (ng * 4 + q) * 8 + (t15 & 7);
                ldsm_x2(bhf[q][0], bhf[q][1], smem_u32(&sKh[r * FPAD + col]));
                ldsm_x2(blf[q][0], blf[q][1], smem_u32(&sKl[r * FPAD + col]));
            }
#pragma unroll
            for (int q = 0; q < 4; ++q) {
                float* cc = c[ng * 4 + q];
                mma_bf16(cc, qh[ks], bhf[q]);
                mma_bf16(cc, qh[ks], blf[q]);
                mma_bf16(cc, ql[ks], bhf[q]);
            }
        }
    }
}

__global__ __launch_bounds__(256, 1)
void fused_attn(float* __restrict__ att) {
    const int bh = blockIdx.y;
    const int b  = bh >> 4;
    const int h  = bh & 15;
    const int i0 = blockIdx.x * 128;

    extern __shared__ __nv_bfloat16 sm[];
    __nv_bfloat16* sQh = sm;
    __nv_bfloat16* sQl = sm + TILEB;
    __nv_bfloat16* sKh[2] = { sm + 2 * TILEB, sm + 4 * TILEB };
    __nv_bfloat16* sKl[2] = { sm + 3 * TILEB, sm + 5 * TILEB };
    __nv_bfloat16* sVh[2] = { sm + 6 * TILEB, sm + 8 * TILEB };
    __nv_bfloat16* sVl[2] = { sm + 7 * TILEB, sm + 9 * TILEB };
    uint32_t aKh[2] = { smem_u32(sKh[0]), smem_u32(sKh[1]) };
    uint32_t aKl[2] = { smem_u32(sKl[0]), smem_u32(sKl[1]) };
    uint32_t aVh[2] = { smem_u32(sVh[0]), smem_u32(sVh[1]) };
    uint32_t aVl[2] = { smem_u32(sVl[0]), smem_u32(sVl[1]) };

    const int tid  = threadIdx.x;
    const int wid  = tid >> 5;
    const int lane = tid & 31;
    const size_t base = ((size_t)b * T) * DIM + h * HD;
    float* arow = att + (size_t)bh * T * T;
    const int ntiles = i0 / 128 + 1;

    // ---- Load Q tile (regular) + prefetch K tile 0 (async) ----
#pragma unroll
    for (int i = 0; i < 4; ++i) {
        const int idx = tid + i * 256;
        const int row = idx >> 3, c8 = (idx & 7) * 8;
        const size_t off = base + (size_t)(i0 + row) * DIM + c8;
        *(uint4*)&sQh[row * FPAD + c8] = *(const uint4*)(g_qhi + off);
        *(uint4*)&sQl[row * FPAD + c8] = *(const uint4*)(g_qlo + off);
    }
    cp_tile(aKh[0], aKl[0], g_khi, g_klo, base, tid);
    cp_commit();
    __syncthreads();

    uint32_t qh[4][4], ql[4][4];
#pragma unroll
    for (int ks = 0; ks < 4; ++ks) {
        const int r   = wid * 16 + (lane & 15);
        const int col = ks * 16 + ((lane >> 4) << 3);
        ldsm_x4(qh[ks][0], qh[ks][1], qh[ks][2], qh[ks][3], smem_u32(&sQh[r * FPAD + col]));
        ldsm_x4(ql[ks][0], ql[ks][1], ql[ks][2], ql[ks][3], smem_u32(&sQl[r * FPAD + col]));
    }

    const int row_lo = (wid << 4) + (lane >> 2);
    float m0 = -1e30f, m1 = -1e30f, l0 = 0.f, l1 = 0.f;

    // ---- Pass A: exact row max + sum (log2 domain) ----
    for (int t = 0; t < ntiles; ++t) {
        const int bf = t & 1;
        if (t + 1 < ntiles) {
            cp_tile(aKh[bf ^ 1], aKl[bf ^ 1], g_khi, g_klo,
                    base + (size_t)(t + 1) * 128 * DIM, tid);
            cp_commit();
            cp_wait<1>();
        } else {
            cp_wait<0>();
        }
        __syncthreads();

        float c[16][4];
        compute_scores(sKh[bf], sKl[bf], qh, ql, lane, c);

        const bool diag = (t * 128 == i0);
        float tm0 = -1e30f, tm1 = -1e30f;
#pragma unroll
        for (int nt = 0; nt < 16; ++nt) {
            float s0 = c[nt][0], s1 = c[nt][1], s2 = c[nt][2], s3 = c[nt][3];
            if (diag) {
                const int c0 = nt * 8 + ((lane & 3) << 1);
                if (c0     > row_lo)     s0 = -1e30f;
                if (c0 + 1 > row_lo)     s1 = -1e30f;
                if (c0     > row_lo + 8) s2 = -1e30f;
                if (c0 + 1 > row_lo + 8) s3 = -1e30f;
            }
            c[nt][0] = s0; c[nt][1] = s1; c[nt][2] = s2; c[nt][3] = s3;
            tm0 = fmaxf(tm0, fmaxf(s0, s1));
            tm1 = fmaxf(tm1, fmaxf(s2, s3));
        }
        tm0 = fmaxf(tm0, __shfl_xor_sync(0xffffffff, tm0, 1));
        tm0 = fmaxf(tm0, __shfl_xor_sync(0xffffffff, tm0, 2));
        tm1 = fmaxf(tm1, __shfl_xor_sync(0xffffffff, tm1, 1));
        tm1 = fmaxf(tm1, __shfl_xor_sync(0xffffffff, tm1, 2));
        const float mn0 = fmaxf(m0, tm0);
        const float mn1 = fmaxf(m1, tm1);
        float sm0 = 0.f, sm1 = 0.f;
#pragma unroll
        for (int nt = 0; nt < 16; ++nt) {
            sm0 += exp2f(c[nt][0] - mn0) + exp2f(c[nt][1] - mn0);
            sm1 += exp2f(c[nt][2] - mn1) + exp2f(c[nt][3] - mn1);
        }
        sm0 += __shfl_xor_sync(0xffffffff, sm0, 1);
        sm0 += __shfl_xor_sync(0xffffffff, sm0, 2);
        sm1 += __shfl_xor_sync(0xffffffff, sm1, 1);
        sm1 += __shfl_xor_sync(0xffffffff, sm1, 2);
        l0 = l0 * exp2f(m0 - mn0) + sm0;  m0 = mn0;
        l1 = l1 * exp2f(m1 - mn1) + sm1;  m1 = mn1;
        __syncthreads();
    }
    const float inv0 = 1.f / l0;
    const float inv1 = 1.f / l1;

    // ---- Pass B: recompute, write att, accumulate y = P@V ----
    cp_tile(aKh[0], aKl[0], g_khi, g_klo, base, tid);
    cp_tile(aVh[0], aVl[0], g_vhi, g_vlo, base, tid);
    cp_commit();

    float y[8][4] = {};
    for (int t = 0; t < ntiles; ++t) {
        const int bf = t & 1;
        if (t + 1 < ntiles) {
            const size_t gb = base + (size_t)(t + 1) * 128 * DIM;
            cp_tile(aKh[bf ^ 1], aKl[bf ^ 1], g_khi, g_klo, gb, tid);
            cp_tile(aVh[bf ^ 1], aVl[bf ^ 1], g_vhi, g_vlo, gb, tid);
            cp_commit();
            cp_wait<1>();
        } else {
            cp_wait<0>();
        }
        __syncthreads();

        float c[16][4];
        compute_scores(sKh[bf], sKl[bf], qh, ql, lane, c);

        const int j0 = t * 128;
        const bool diag = (j0 == i0);
#pragma unroll
        for (int nt = 0; nt < 16; ++nt) {
            float p0 = exp2f(c[nt][0] - m0) * inv0;
            float p1 = exp2f(c[nt][1] - m0) * inv0;
            float p2 = exp2f(c[nt][2] - m1) * inv1;
            float p3 = exp2f(c[nt][3] - m1) * inv1;
            if (diag) {
                const int c0 = nt * 8 + ((lane & 3) << 1);
                if (c0     > row_lo)     p0 = 0.f;
                if (c0 + 1 > row_lo)     p1 = 0.f;
                if (c0     > row_lo + 8) p2 = 0.f;
                if (c0 + 1 > row_lo + 8) p3 = 0.f;
            }
            c[nt][0] = p0; c[nt][1] = p1; c[nt][2] = p2; c[nt][3] = p3;
            const int cc = j0 + nt * 8 + ((lane & 3) << 1);
            *(float2*)(arow + (size_t)(i0 + row_lo) * T + cc)     = make_float2(p0, p1);
            *(float2*)(arow + (size_t)(i0 + row_lo + 8) * T + cc) = make_float2(p2, p3);
        }

#pragma unroll
        for (int kg = 0; kg < 8; ++kg) {
            const int f0 = 2 * kg, f1 = 2 * kg + 1;
            uint32_t ah[4], al[4];
            pack2(c[f0][0], c[f0][1], ah[0], al[0]);
            pack2(c[f0][2], c[f0][3], ah[1], al[1]);
            pack2(c[f1][0], c[f1][1], ah[2], al[2]);
            pack2(c[f1][2], c[f1][3], ah[3], al[3]);
            const int kr = kg * 16 + (lane & 15);
#pragma unroll
            for (int nt2 = 0; nt2 < 8; ++nt2) {
                uint32_t vh[2], vl[2];
                ldsm_x2_t(vh[0], vh[1], smem_u32(&sVh[bf][kr * FPAD + nt2 * 8]));
                ldsm_x2_t(vl[0], vl[1], smem_u32(&sVl[bf][kr * FPAD + nt2 * 8]));
                mma_bf16(y[nt2], ah, vh);
                mma_bf16(y[nt2], ah, vl);
                mma_bf16(y[nt2], al, vh);
            }
        }
        __syncthreads();
    }

    // ---- Write y as bf16 hi/lo (feeds the output projection) ----
#pragma unroll
    for (int nt2 = 0; nt2 < 8; ++nt2) {
        const int r0 = i0 + row_lo;
        const size_t off = ((size_t)b * T + r0) * DIM + h * HD + nt2 * 8 + ((lane & 3) << 1);
        uint32_t hp, lp;
        pack2(y[nt2][0], y[nt2][1], hp, lp);
        *(uint32_t*)(g_yhi + off) = hp;
        *(uint32_t*)(g_ylo + off) = lp;
        pack2(y[nt2][2], y[nt2][3], hp, lp);
        *(uint32_t*)(g_yhi + off + 8 * DIM) = hp;
        *(uint32_t*)(g_ylo + off + 8 * DIM) = lp;
    }

    // ---- Zero-fill att cols [i0+128, T) for this row block ----
    const int start = i0 + 128;
    if (start < T) {
        const int spanv = (T - start) >> 2;
        for (int r = wid; r < 128; r += 8) {
            float* dst = arow + (size_t)(i0 + r) * T + start;
            for (int cq = lane; cq < spanv; cq += 32)
                *(float4*)(dst + cq * 4) = make_float4(0.f, 0.f, 0.f, 0.f);
        }
    }
}

// ===========================================================================
extern "C" void kernel_launch(void* const* d_in, const int* in_sizes, int n_in,
                              void* d_out, int out_size) {
    const float* Q  = (const float*)d_in[0];
    const float* K  = (const float*)d_in[1];
    const float* V  = (const float*)d_in[2];
    const float* Wq = (const float*)d_in[3];
    const float* Wk = (const float*)d_in[4];
    const float* Wv = (const float*)d_in[5];
    const float* Wo = (const float*)d_in[6];
    float* out = (float*)d_out;

    float* gfb;
    cudaGetSymbolAddress((void**)&gfb, g_att_fb);
    float* att = ((size_t)out_size >= Y_SIZE + ATT_SIZE) ? (out + Y_SIZE) : gfb;

    cudaFuncSetAttribute(fused_attn, cudaFuncAttributeMaxDynamicSharedMemorySize,
                         FUSED_SMEM);
    cudaFuncSetAttribute(gemm_qkv, cudaFuncAttributeMaxDynamicSharedMemorySize,
                         GEMM_SMEM);
    cudaFuncSetAttribute(gemm_out, cudaFuncAttributeMaxDynamicSharedMemorySize,
                         GEMM_SMEM);

    dim3 thr(256);

    // 0) fp32 -> bf16 hi/lo conversion for inputs + weights
    conv_split<<<dim3(512, 7), thr>>>(Q, K, V, Wq, Wk, Wv, Wo);

    // 1) Merged Q/K/V projections (pure bf16, cp.async double-buffered)
    dim3 gQKV(NDIM / 128, BT / 128, 3);   // (8, 32, 3)
    gemm_qkv<<<gQKV, thr, GEMM_SMEM>>>();

    // 2) Fused scores + softmax + att + AV
    dim3 gFuse(T / 128, B * H);           // (16, 32)
    fused_attn<<<gFuse, thr, FUSED_SMEM>>>(att);

    // 3) out = y @ Wo^T (pure bf16)
    dim3 gOut(NDIM / 128, BT / 128);
    gemm_out<<<gOut, thr, GEMM_SMEM>>>(out);
}

// round 15
// speedup vs baseline: 1.0028x; 1.0028x over previous
#include <cuda_runtime.h>
#include <cuda_bf16.h>
#include <cstdint>
#include <cstddef>

// Problem constants
constexpr int B   = 2;
constexpr int T   = 2048;
constexpr int DIM = 1024;
constexpr int H   = 16;
constexpr int HD  = 64;
constexpr int BT  = B * T;        // 4096
constexpr float SCALE = 0.03125f; // 1/sqrt(1024)
constexpr float LOG2E = 1.44269504088896341f;
constexpr float QMUL  = SCALE * LOG2E;   // fold into q projection

constexpr size_t Y_SIZE   = (size_t)BT * DIM;
constexpr size_t ATT_SIZE = (size_t)B * H * T * T;

// Scratch (allocation-free rule: __device__ globals)
__device__ __nv_bfloat16 g_qhi[BT * DIM];
__device__ __nv_bfloat16 g_qlo[BT * DIM];
__device__ __nv_bfloat16 g_khi[BT * DIM];
__device__ __nv_bfloat16 g_klo[BT * DIM];
__device__ __nv_bfloat16 g_vhi[BT * DIM];
__device__ __nv_bfloat16 g_vlo[BT * DIM];
__device__ float g_y[BT * DIM];
__device__ float g_att_fb[ATT_SIZE];   // fallback att if out buffer lacks room

// ===========================================================================
// PTX helpers (standard ISA — legal on plain sm_103 target)
// ===========================================================================
__device__ __forceinline__ uint32_t smem_u32(const void* p) {
    uint32_t a;
    asm("{ .reg .u64 t; cvta.to.shared.u64 t, %1; cvt.u32.u64 %0, t; }" : "=r"(a) : "l"(p));
    return a;
}
__device__ __forceinline__ void ldsm_x4(uint32_t& r0, uint32_t& r1, uint32_t& r2,
                                        uint32_t& r3, uint32_t addr) {
    asm volatile("ldmatrix.sync.aligned.m8n8.x4.shared.b16 {%0,%1,%2,%3}, [%4];"
                 : "=r"(r0), "=r"(r1), "=r"(r2), "=r"(r3) : "r"(addr));
}
__device__ __forceinline__ void ldsm_x2(uint32_t& r0, uint32_t& r1, uint32_t addr) {
    asm volatile("ldmatrix.sync.aligned.m8n8.x2.shared.b16 {%0,%1}, [%2];"
                 : "=r"(r0), "=r"(r1) : "r"(addr));
}
__device__ __forceinline__ void ldsm_x2_t(uint32_t& r0, uint32_t& r1, uint32_t addr) {
    asm volatile("ldmatrix.sync.aligned.m8n8.x2.trans.shared.b16 {%0,%1}, [%2];"
                 : "=r"(r0), "=r"(r1) : "r"(addr));
}
__device__ __forceinline__ void mma_bf16(float* c, const uint32_t* a, const uint32_t* b) {
    asm volatile(
        "mma.sync.aligned.m16n8k16.row.col.f32.bf16.bf16.f32 "
        "{%0,%1,%2,%3}, {%4,%5,%6,%7}, {%8,%9}, {%0,%1,%2,%3};"
        : "+f"(c[0]), "+f"(c[1]), "+f"(c[2]), "+f"(c[3])
        : "r"(a[0]), "r"(a[1]), "r"(a[2]), "r"(a[3]), "r"(b[0]), "r"(b[1]));
}
__device__ __forceinline__ void cp16(uint32_t dst, const void* src) {
    asm volatile("cp.async.ca.shared.global [%0], [%1], 16;" :: "r"(dst), "l"(src));
}
__device__ __forceinline__ void cp_commit() {
    asm volatile("cp.async.commit_group;" ::: "memory");
}
template <int N>
__device__ __forceinline__ void cp_wait() {
    asm volatile("cp.async.wait_group %0;" :: "n"(N) : "memory");
}
__device__ __forceinline__ void split4(float4 v, uint2& hi, uint2& lo) {
    __nv_bfloat16 h0 = __float2bfloat16_rn(v.x);
    __nv_bfloat16 h1 = __float2bfloat16_rn(v.y);
    __nv_bfloat16 h2 = __float2bfloat16_rn(v.z);
    __nv_bfloat16 h3 = __float2bfloat16_rn(v.w);
    __nv_bfloat16 l0 = __float2bfloat16_rn(v.x - __bfloat162float(h0));
    __nv_bfloat16 l1 = __float2bfloat16_rn(v.y - __bfloat162float(h1));
    __nv_bfloat16 l2 = __float2bfloat16_rn(v.z - __bfloat162float(h2));
    __nv_bfloat16 l3 = __float2bfloat16_rn(v.w - __bfloat162float(h3));
    __nv_bfloat162 hA = {h0, h1}, hB = {h2, h3}, lA = {l0, l1}, lB = {l2, l3};
    hi = make_uint2(*(uint32_t*)&hA, *(uint32_t*)&hB);
    lo = make_uint2(*(uint32_t*)&lA, *(uint32_t*)&lB);
}
__device__ __forceinline__ void pack2(float x, float y, uint32_t& hi, uint32_t& lo) {
    __nv_bfloat16 hx = __float2bfloat16_rn(x);
    __nv_bfloat16 hy = __float2bfloat16_rn(y);
    __nv_bfloat162 hp = {hx, hy};
    __nv_bfloat162 lp = {__float2bfloat16_rn(x - __bfloat162float(hx)),
                         __float2bfloat16_rn(y - __bfloat162float(hy))};
    hi = *(uint32_t*)&hp;
    lo = *(uint32_t*)&lp;
}

// ===========================================================================
// bf16x3 split GEMM core: C = A @ W^T, 128x128 tile, K-chunk 32.
// fp32 LDG + in-register split (round-13 proven schedule), but with
// DOUBLE-BUFFERED smem and ONE __syncthreads per chunk:
//   LDG(next) -> MMA(buf A) -> convert+STS(buf B) -> sync
// ===========================================================================
constexpr int KDIM = 1024;
constexpr int NDIM = 1024;
constexpr int KCH  = 32;
constexpr int NCHG = KDIM / KCH;
constexpr int SPAD = 40;
constexpr int GBUF = 128 * SPAD;                 // elems per operand array
constexpr int GEMM_SMEM = 2 * 4 * GBUF * 2;      // 2 bufs x 4 arrays x bf16 = 81,920 B

struct EpiSplit {           // write bf16 hi/lo with scale
    __nv_bfloat16* Chi;
    __nv_bfloat16* Clo;
    float mul;
    __device__ __forceinline__ void operator()(int r0, int cc, const float* cf) const {
#pragma unroll
        for (int rr = 0; rr < 2; ++rr) {
            const size_t off = (size_t)(r0 + rr * 8) * NDIM + cc;
            uint32_t hp, lp;
            pack2(cf[rr * 2] * mul, cf[rr * 2 + 1] * mul, hp, lp);
            *(uint32_t*)(Chi + off) = hp;
            *(uint32_t*)(Clo + off) = lp;
        }
    }
};
struct EpiF32 {             // write fp32
    float* C;
    __device__ __forceinline__ void operator()(int r0, int cc, const float* cf) const {
        *(float2*)(C + (size_t)r0 * NDIM + cc)       = make_float2(cf[0], cf[1]);
        *(float2*)(C + (size_t)(r0 + 8) * NDIM + cc) = make_float2(cf[2], cf[3]);
    }
};

template <typename EPI>
__device__ __forceinline__ void gemm_core(const float* __restrict__ A,
                                          const float* __restrict__ W,
                                          int m0, int n0, EPI epi) {
    extern __shared__ __nv_bfloat16 sg[];
    // layout: [buf(2)][arr(4: Ahi,Alo,Whi,Wlo)][128*SPAD]
    const int tid  = threadIdx.x;
    const int wid  = tid >> 5;
    const int lane = tid & 31;
    const int warp_m = wid >> 2;
    const int warp_n = wid & 3;

    __nv_bfloat16* sAhi[2] = { sg + 0 * GBUF, sg + 4 * GBUF };
    __nv_bfloat16* sAlo[2] = { sg + 1 * GBUF, sg + 5 * GBUF };
    __nv_bfloat16* sWhi[2] = { sg + 2 * GBUF, sg + 6 * GBUF };
    __nv_bfloat16* sWlo[2] = { sg + 3 * GBUF, sg + 7 * GBUF };

    // per-thread load coords (same pattern as round-13)
    const int lrow0 = (tid * 2)     >> 3;   // but keep exact round-13 indexing below
    (void)lrow0;

    float c[4][4][4] = {};
    float4 pa[4], pw[4];

    // Load chunk 0 into registers, convert+store into buf 0
#pragma unroll
    for (int i = 0; i < 4; ++i) {
        const int idx = tid + i * 256;
        const int row = idx >> 3, c4 = (idx & 7) * 4;
        pa[i] = *(const float4*)(A + (size_t)(m0 + row) * KDIM + c4);
        pw[i] = *(const float4*)(W + (size_t)(n0 + row) * KDIM + c4);
    }
#pragma unroll
    for (int i = 0; i < 4; ++i) {
        const int idx = tid + i * 256;
        const int row = idx >> 3, c4 = (idx & 7) * 4;
        uint2 hi, lo;
        split4(pa[i], hi, lo);
        *(uint2*)&sAhi[0][row * SPAD + c4] = hi;
        *(uint2*)&sAlo[0][row * SPAD + c4] = lo;
        split4(pw[i], hi, lo);
        *(uint2*)&sWhi[0][row * SPAD + c4] = hi;
        *(uint2*)&sWlo[0][row * SPAD + c4] = lo;
    }
    __syncthreads();

    for (int ch = 0; ch < NCHG; ++ch) {
        const int bf = ch & 1;

        // LDG next chunk (latency hidden behind the MMA below)
        if (ch + 1 < NCHG) {
            const int k0n = (ch + 1) * KCH;
#pragma unroll
            for (int i = 0; i < 4; ++i) {
                const int idx = tid + i * 256;
                const int row = idx >> 3, c4 = (idx & 7) * 4;
                pa[i] = *(const float4*)(A + (size_t)(m0 + row) * KDIM + k0n + c4);
                pw[i] = *(const float4*)(W + (size_t)(n0 + row) * KDIM + k0n + c4);
            }
        }

        // MMA on buf[bf]
#pragma unroll
        for (int ks = 0; ks < 2; ++ks) {
            const int kc = ks * 16;
            uint32_t ah[4][4], al[4][4], bh[4][2], bl[4][2];
#pragma unroll
            for (int mt = 0; mt < 4; ++mt) {
                const int r   = warp_m * 64 + mt * 16 + (lane & 15);
                const int col = kc + ((lane >> 4) << 3);
                ldsm_x4(ah[mt][0], ah[mt][1], ah[mt][2], ah[mt][3],
                        smem_u32(&sAhi[bf][r * SPAD + col]));
                ldsm_x4(al[mt][0], al[mt][1], al[mt][2], al[mt][3],
                        smem_u32(&sAlo[bf][r * SPAD + col]));
            }
#pragma unroll
            for (int nt = 0; nt < 4; ++nt) {
                const int t   = lane & 15;
                const int r   = warp_n * 32 + nt * 8 + (t & 7);
                const int col = kc + ((t >> 3) << 3);
                ldsm_x2(bh[nt][0], bh[nt][1], smem_u32(&sWhi[bf][r * SPAD + col]));
                ldsm_x2(bl[nt][0], bl[nt][1], smem_u32(&sWlo[bf][r * SPAD + col]));
            }
#pragma unroll
            for (int mt = 0; mt < 4; ++mt)
#pragma unroll
                for (int nt = 0; nt < 4; ++nt) {
                    mma_bf16(c[mt][nt], ah[mt], bh[nt]);
                    mma_bf16(c[mt][nt], ah[mt], bl[nt]);
                    mma_bf16(c[mt][nt], al[mt], bh[nt]);
                }
        }

        // Convert + store next chunk into the other buffer
        if (ch + 1 < NCHG) {
#pragma unroll
            for (int i = 0; i < 4; ++i) {
                const int idx = tid + i * 256;
                const int row = idx >> 3, c4 = (idx & 7) * 4;
                uint2 hi, lo;
                split4(pa[i], hi, lo);
                *(uint2*)&sAhi[bf ^ 1][row * SPAD + c4] = hi;
                *(uint2*)&sAlo[bf ^ 1][row * SPAD + c4] = lo;
                split4(pw[i], hi, lo);
                *(uint2*)&sWhi[bf ^ 1][row * SPAD + c4] = hi;
                *(uint2*)&sWlo[bf ^ 1][row * SPAD + c4] = lo;
            }
        }
        __syncthreads();
    }

#pragma unroll
    for (int mt = 0; mt < 4; ++mt) {
        const int r0 = m0 + warp_m * 64 + mt * 16 + (lane >> 2);
#pragma unroll
        for (int nt = 0; nt < 4; ++nt) {
            const int cc = n0 + warp_n * 32 + nt * 8 + (lane & 3) * 2;
            epi(r0, cc, c[mt][nt]);
        }
    }
}

// Merged Q/K/V projection (z selects), writing pre-split bf16; Q pre-scaled.
__global__ __launch_bounds__(256, 1)
void gemm_qkv(const float* __restrict__ Q, const float* __restrict__ K,
              const float* __restrict__ V, const float* __restrict__ Wq,
              const float* __restrict__ Wk, const float* __restrict__ Wv) {
    const int z = blockIdx.z;
    const float* A = (z == 0) ? Q : (z == 1) ? K : V;
    const float* W = (z == 0) ? Wq : (z == 1) ? Wk : Wv;
    EpiSplit epi;
    epi.Chi = (z == 0) ? g_qhi : (z == 1) ? g_khi : g_vhi;
    epi.Clo = (z == 0) ? g_qlo : (z == 1) ? g_klo : g_vlo;
    epi.mul = (z == 0) ? QMUL : 1.0f;
    gemm_core(A, W, blockIdx.y * 128, blockIdx.x * 128, epi);
}

// Output projection: fp32 C.
__global__ __launch_bounds__(256, 1)
void gemm_out(const float* __restrict__ A, const float* __restrict__ W,
              float* __restrict__ C) {
    EpiF32 epi;
    epi.C = C;
    gemm_core(A, W, blockIdx.y * 128, blockIdx.x * 128, epi);
}

// ===========================================================================
// Fused flash attention with cp.async double-buffered K/V tiles.
// Scores are in log2 units (q pre-scaled by SCALE*log2e) -> exp2f.
// Heavy-first block order: largest causal row-blocks launch first.
// ===========================================================================
constexpr int FPAD  = 72;
constexpr int TILEB = 128 * FPAD;                 // bf16 elems per buffer
constexpr int FUSED_SMEM = 10 * TILEB * 2;        // Q(2) + K(4) + V(4) = 184,320 B

// async-copy one 128x64 hi/lo tile pair into smem buffers
__device__ __forceinline__ void cp_tile(uint32_t dh, uint32_t dl,
                                        const __nv_bfloat16* __restrict__ gh,
                                        const __nv_bfloat16* __restrict__ gl,
                                        size_t gbase, int tid) {
#pragma unroll
    for (int i = 0; i < 4; ++i) {
        const int idx = tid + i * 256;
        const int row = idx >> 3, c8 = (idx & 7) * 8;
        const size_t off = gbase + (size_t)row * DIM + c8;
        const uint32_t d = (uint32_t)((row * FPAD + c8) * 2);
        cp16(dh + d, gh + off);
        cp16(dl + d, gl + off);
    }
}

__device__ __forceinline__ void compute_scores(
    const __nv_bfloat16* __restrict__ sKh, const __nv_bfloat16* __restrict__ sKl,
    const uint32_t qh[4][4], const uint32_t ql[4][4],
    int lane, float c[16][4]) {
#pragma unroll
    for (int nt = 0; nt < 16; ++nt) {
        c[nt][0] = 0.f; c[nt][1] = 0.f; c[nt][2] = 0.f; c[nt][3] = 0.f;
    }
    const int t15 = lane & 15;
#pragma unroll
    for (int ks = 0; ks < 4; ++ks) {
        const int col = ks * 16 + ((t15 >> 3) << 3);
#pragma unroll
        for (int ng = 0; ng < 4; ++ng) {
            uint32_t bhf[4][2], blf[4][2];
#pragma unroll
            for (int q = 0; q < 4; ++q) {
                const int r = (ng * 4 + q) * 8 + (t15 & 7);
                ldsm_x2(bhf[q][0], bhf[q][1], smem_u32(&sKh[r * FPAD + col]));
                ldsm_x2(blf[q][0], blf[q][1], smem_u32(&sKl[r * FPAD + col]));
            }
#pragma unroll
            for (int q = 0; q < 4; ++q) {
                float* cc = c[ng * 4 + q];
                mma_bf16(cc, qh[ks], bhf[q]);
                mma_bf16(cc, qh[ks], blf[q]);
                mma_bf16(cc, ql[ks], bhf[q]);
            }
        }
    }
}

__global__ __launch_bounds__(256, 1)
void fused_attn(float* __restrict__ att) {
    const int bh = blockIdx.y;
    const int b  = bh >> 4;
    const int h  = bh & 15;
    // Heavy-first: largest i0 (most causal tiles) launches first
    const int i0 = (int)(gridDim.x - 1 - blockIdx.x) * 128;

    extern __shared__ __nv_bfloat16 sm[];
    __nv_bfloat16* sQh = sm;
    __nv_bfloat16* sQl = sm + TILEB;
    __nv_bfloat16* sKh[2] = { sm + 2 * TILEB, sm + 4 * TILEB };
    __nv_bfloat16* sKl[2] = { sm + 3 * TILEB, sm + 5 * TILEB };
    __nv_bfloat16* sVh[2] = { sm + 6 * TILEB, sm + 8 * TILEB };
    __nv_bfloat16* sVl[2] = { sm + 7 * TILEB, sm + 9 * TILEB };
    uint32_t aKh[2] = { smem_u32(sKh[0]), smem_u32(sKh[1]) };
    uint32_t aKl[2] = { smem_u32(sKl[0]), smem_u32(sKl[1]) };
    uint32_t aVh[2] = { smem_u32(sVh[0]), smem_u32(sVh[1]) };
    uint32_t aVl[2] = { smem_u32(sVl[0]), smem_u32(sVl[1]) };

    const int tid  = threadIdx.x;
    const int wid  = tid >> 5;
    const int lane = tid & 31;
    const size_t base = ((size_t)b * T) * DIM + h * HD;
    float* arow = att + (size_t)bh * T * T;
    const int ntiles = i0 / 128 + 1;

    // ---- Load Q tile (regular) + prefetch K tile 0 (async) ----
#pragma unroll
    for (int i = 0; i < 4; ++i) {
        const int idx = tid + i * 256;
        const int row = idx >> 3, c8 = (idx & 7) * 8;
        const size_t off = base + (size_t)(i0 + row) * DIM + c8;
        *(uint4*)&sQh[row * FPAD + c8] = *(const uint4*)(g_qhi + off);
        *(uint4*)&sQl[row * FPAD + c8] = *(const uint4*)(g_qlo + off);
    }
    cp_tile(aKh[0], aKl[0], g_khi, g_klo, base, tid);
    cp_commit();
    __syncthreads();

    uint32_t qh[4][4], ql[4][4];
#pragma unroll
    for (int ks = 0; ks < 4; ++ks) {
        const int r   = wid * 16 + (lane & 15);
        const int col = ks * 16 + ((lane >> 4) << 3);
        ldsm_x4(qh[ks][0], qh[ks][1], qh[ks][2], qh[ks][3], smem_u32(&sQh[r * FPAD + col]));
        ldsm_x4(ql[ks][0], ql[ks][1], ql[ks][2], ql[ks][3], smem_u32(&sQl[r * FPAD + col]));
    }

    const int row_lo = (wid << 4) + (lane >> 2);
    float m0 = -1e30f, m1 = -1e30f, l0 = 0.f, l1 = 0.f;

    // ---- Pass A: exact row max + sum (log2 domain) ----
    for (int t = 0; t < ntiles; ++t) {
        const int bf = t & 1;
        if (t + 1 < ntiles) {
            cp_tile(aKh[bf ^ 1], aKl[bf ^ 1], g_khi, g_klo,
                    base + (size_t)(t + 1) * 128 * DIM, tid);
            cp_commit();
            cp_wait<1>();
        } else {
            cp_wait<0>();
        }
        __syncthreads();

        float c[16][4];
        compute_scores(sKh[bf], sKl[bf], qh, ql, lane, c);

        const bool diag = (t * 128 == i0);
        float tm0 = -1e30f, tm1 = -1e30f;
#pragma unroll
        for (int nt = 0; nt < 16; ++nt) {
            float s0 = c[nt][0], s1 = c[nt][1], s2 = c[nt][2], s3 = c[nt][3];
            if (diag) {
                const int c0 = nt * 8 + ((lane & 3) << 1);
                if (c0     > row_lo)     s0 = -1e30f;
                if (c0 + 1 > row_lo)     s1 = -1e30f;
                if (c0     > row_lo + 8) s2 = -1e30f;
                if (c0 + 1 > row_lo + 8) s3 = -1e30f;
            }
            c[nt][0] = s0; c[nt][1] = s1; c[nt][2] = s2; c[nt][3] = s3;
            tm0 = fmaxf(tm0, fmaxf(s0, s1));
            tm1 = fmaxf(tm1, fmaxf(s2, s3));
        }
        tm0 = fmaxf(tm0, __shfl_xor_sync(0xffffffff, tm0, 1));
        tm0 = fmaxf(tm0, __shfl_xor_sync(0xffffffff, tm0, 2));
        tm1 = fmaxf(tm1, __shfl_xor_sync(0xffffffff, tm1, 1));
        tm1 = fmaxf(tm1, __shfl_xor_sync(0xffffffff, tm1, 2));
        const float mn0 = fmaxf(m0, tm0);
        const float mn1 = fmaxf(m1, tm1);
        float sm0 = 0.f, sm1 = 0.f;
#pragma unroll
        for (int nt = 0; nt < 16; ++nt) {
            sm0 += exp2f(c[nt][0] - mn0) + exp2f(c[nt][1] - mn0);
            sm1 += exp2f(c[nt][2] - mn1) + exp2f(c[nt][3] - mn1);
        }
        sm0 += __shfl_xor_sync(0xffffffff, sm0, 1);
        sm0 += __shfl_xor_sync(0xffffffff, sm0, 2);
        sm1 += __shfl_xor_sync(0xffffffff, sm1, 1);
        sm1 += __shfl_xor_sync(0xffffffff, sm1, 2);
        l0 = l0 * exp2f(m0 - mn0) + sm0;  m0 = mn0;
        l1 = l1 * exp2f(m1 - mn1) + sm1;  m1 = mn1;
        __syncthreads();
    }
    const float inv0 = 1.f / l0;
    const float inv1 = 1.f / l1;

    // ---- Pass B: recompute, write att, accumulate y = P@V ----
    cp_tile(aKh[0], aKl[0], g_khi, g_klo, base, tid);
    cp_tile(aVh[0], aVl[0], g_vhi, g_vlo, base, tid);
    cp_commit();

    float y[8][4] = {};
    for (int t = 0; t < ntiles; ++t) {
        const int bf = t & 1;
        if (t + 1 < ntiles) {
            const size_t gb = base + (size_t)(t + 1) * 128 * DIM;
            cp_tile(aKh[bf ^ 1], aKl[bf ^ 1], g_khi, g_klo, gb, tid);
            cp_tile(aVh[bf ^ 1], aVl[bf ^ 1], g_vhi, g_vlo, gb, tid);
            cp_commit();
            cp_wait<1>();
        } else {
            cp_wait<0>();
        }
        __syncthreads();

        float c[16][4];
        compute_scores(sKh[bf], sKl[bf], qh, ql, lane, c);

        const int j0 = t * 128;
        const bool diag = (j0 == i0);
#pragma unroll
        for (int nt = 0; nt < 16; ++nt) {
            float p0 = exp2f(c[nt][0] - m0) * inv0;
            float p1 = exp2f(c[nt][1] - m0) * inv0;
            float p2 = exp2f(c[nt][2] - m1) * inv1;
            float p3 = exp2f(c[nt][3] - m1) * inv1;
            if (diag) {
                const int c0 = nt * 8 + ((lane & 3) << 1);
                if (c0     > row_lo)     p0 = 0.f;
                if (c0 + 1 > row_lo)     p1 = 0.f;
                if (c0     > row_lo + 8) p2 = 0.f;
                if (c0 + 1 > row_lo + 8) p3 = 0.f;
            }
            c[nt][0] = p0; c[nt][1] = p1; c[nt][2] = p2; c[nt][3] = p3;
            const int cc = j0 + nt * 8 + ((lane & 3) << 1);
            *(float2*)(arow + (size_t)(i0 + row_lo) * T + cc)     = make_float2(p0, p1);
            *(float2*)(arow + (size_t)(i0 + row_lo + 8) * T + cc) = make_float2(p2, p3);
        }

#pragma unroll
        for (int kg = 0; kg < 8; ++kg) {
            const int f0 = 2 * kg, f1 = 2 * kg + 1;
            uint32_t ah[4], al[4];
            pack2(c[f0][0], c[f0][1], ah[0], al[0]);
            pack2(c[f0][2], c[f0][3], ah[1], al[1]);
            pack2(c[f1][0], c[f1][1], ah[2], al[2]);
            pack2(c[f1][2], c[f1][3], ah[3], al[3]);
            const int kr = kg * 16 + (lane & 15);
#pragma unroll
            for (int nt2 = 0; nt2 < 8; ++nt2) {
                uint32_t vh[2], vl[2];
                ldsm_x2_t(vh[0], vh[1], smem_u32(&sVh[bf][kr * FPAD + nt2 * 8]));
                ldsm_x2_t(vl[0], vl[1], smem_u32(&sVl[bf][kr * FPAD + nt2 * 8]));
                mma_bf16(y[nt2], ah, vh);
                mma_bf16(y[nt2], ah, vl);
                mma_bf16(y[nt2], al, vh);
            }
        }
        __syncthreads();
    }

    // ---- Write y ----
#pragma unroll
    for (int nt2 = 0; nt2 < 8; ++nt2) {
        const int r0 = i0 + row_lo;
        float* y0 = g_y + ((size_t)b * T + r0) * DIM + h * HD + nt2 * 8 + ((lane & 3) << 1);
        *(float2*)y0             = make_float2(y[nt2][0], y[nt2][1]);
        *(float2*)(y0 + 8 * DIM) = make_float2(y[nt2][2], y[nt2][3]);
    }

    // ---- Zero-fill att cols [i0+128, T) for this row block ----
    const int start = i0 + 128;
    if (start < T) {
        const int spanv = (T - start) >> 2;
        for (int r = wid; r < 128; r += 8) {
            float* dst = arow + (size_t)(i0 + r) * T + start;
            for (int cq = lane; cq < spanv; cq += 32)
                *(float4*)(dst + cq * 4) = make_float4(0.f, 0.f, 0.f, 0.f);
        }
    }
}

// ===========================================================================
extern "C" void kernel_launch(void* const* d_in, const int* in_sizes, int n_in,
                              void* d_out, int out_size) {
    const float* Q  = (const float*)d_in[0];
    const float* K  = (const float*)d_in[1];
    const float* V  = (const float*)d_in[2];
    const float* Wq = (const float*)d_in[3];
    const float* Wk = (const float*)d_in[4];
    const float* Wv = (const float*)d_in[5];
    const float* Wo = (const float*)d_in[6];
    float* out = (float*)d_out;

    float *gy, *gfb;
    cudaGetSymbolAddress((void**)&gy,  g_y);
    cudaGetSymbolAddress((void**)&gfb, g_att_fb);

    float* att = ((size_t)out_size >= Y_SIZE + ATT_SIZE) ? (out + Y_SIZE) : gfb;

    cudaFuncSetAttribute(fused_attn, cudaFuncAttributeMaxDynamicSharedMemorySize,
                         FUSED_SMEM);
    cudaFuncSetAttribute(gemm_qkv, cudaFuncAttributeMaxDynamicSharedMemorySize,
                         GEMM_SMEM);
    cudaFuncSetAttribute(gemm_out, cudaFuncAttributeMaxDynamicSharedMemorySize,
                         GEMM_SMEM);

    dim3 thr(256);

    // 1) Merged Q/K/V projections (q pre-scaled by SCALE*log2e)
    dim3 gQKV(NDIM / 128, BT / 128, 3);   // (8, 32, 3)
    gemm_qkv<<<gQKV, thr, GEMM_SMEM>>>(Q, K, V, Wq, Wk, Wv);

    // 2) Fused scores + softmax + att + AV (double-buffered cp.async, heavy-first)
    dim3 gFuse(T / 128, B * H);           // (16, 32)
    fused_attn<<<gFuse, thr, FUSED_SMEM>>>(att);

    // 3) out = y @ Wo^T
    dim3 gOut(NDIM / 128, BT / 128);
    gemm_out<<<gOut, thr, GEMM_SMEM>>>(gy, Wo, out);
}